// round 1
// baseline (speedup 1.0000x reference)
#include <cuda_runtime.h>
#include <cuda_bf16.h>

#define SS   1024      // S = 2*max(H,W)
#define HH   512
#define WW   512
#define BB   32
#define OFFC 256       // (S-H)/2 = (S-W)/2

__global__ __launch_bounds__(256)
void gridmask_kernel(const float* __restrict__ img,
                     const float* __restrict__ angles,
                     const int*   __restrict__ gridblock,
                     const int*   __restrict__ start1,
                     const int*   __restrict__ start2,
                     float*       __restrict__ out) {
    __shared__ float rowm[SS];
    __shared__ float colm[SS];
    __shared__ float s_trig[2];

    const int b   = blockIdx.y;
    const int gb  = gridblock[b];
    const int st1 = start1[b];
    const int st2 = start2[b];

    // length = clip(int(gb*0.6 + 0.5), 1, gb-1)  -- match f32 mul then add, truncate
    float lf = __fadd_rn(__fmul_rn((float)gb, 0.6f), 0.5f);
    int length = (int)lf;
    length = min(max(length, 1), gb - 1);
    const int lim = (SS / gb) * gb;   // d // gb < n  <=>  d < n*gb  (given d>=0)

    if (threadIdx.x == 0) {
        float a = angles[b];
        s_trig[0] = cosf(a);
        s_trig[1] = sinf(a);
    }
    // Build separable stripe LUTs (the only integer divisions in the kernel)
    for (int i = threadIdx.x; i < SS; i += blockDim.x) {
        int d1 = i - st1;
        rowm[i] = (d1 >= 0 && d1 < lim && (d1 % gb) < length) ? 1.0f : 0.0f;
        int d2 = i - st2;
        colm[i] = (d2 >= 0 && d2 < lim && (d2 % gb) < length) ? 1.0f : 0.0f;
    }
    __syncthreads();

    const float cosv = s_trig[0];
    const float sinv = s_trig[1];
    const float c = (float)(SS - 1) * 0.5f;   // 511.5

    const int ROWS = 8;
    const int row0 = blockIdx.x * ROWS;
    const float* imgb = img + (size_t)b * HH * WW * 3;
    float*       outb = out + (size_t)b * HH * WW * 3;

    // Each iteration: 4 consecutive pixels = 12 floats = 3 float4 (48B, 16B-aligned)
    const int NGROUPS = (ROWS * WW) / 4;   // 1024
    for (int g = threadIdx.x; g < NGROUPS; g += blockDim.x) {
        const int p0 = g * 4;
        const int h  = row0 + (p0 >> 9);      // / WW
        const int w  = p0 & (WW - 1);
        const float y = (float)(h + OFFC) - c;

        float m[4];
        #pragma unroll
        for (int k = 0; k < 4; k++) {
            float x  = (float)(w + k + OFFC) - c;
            float sx =  cosv * x + sinv * y + c;
            float sy = -sinv * x + cosv * y + c;
            float x0f = floorf(sx), y0f = floorf(sy);
            float fx = sx - x0f,    fy = sy - y0f;
            int x0 = (int)x0f, y0 = (int)y0f;
            // reflect: mod 2S (pow2 -> AND), then fold
            int xm0 = x0 & (2*SS - 1),   xm1 = (x0 + 1) & (2*SS - 1);
            int ym0 = y0 & (2*SS - 1),   ym1 = (y0 + 1) & (2*SS - 1);
            int x0r = (xm0 < SS) ? xm0 : (2*SS - 1 - xm0);
            int x1r = (xm1 < SS) ? xm1 : (2*SS - 1 - xm1);
            int y0r = (ym0 < SS) ? ym0 : (2*SS - 1 - ym0);
            int y1r = (ym1 < SS) ? ym1 : (2*SS - 1 - ym1);
            float r0 = rowm[y0r], r1 = rowm[y1r];
            float c0 = colm[x0r], c1 = colm[x1r];
            // OR of {0,1} masks == max
            float v00 = fmaxf(r0, c0), v01 = fmaxf(r0, c1);
            float v10 = fmaxf(r1, c0), v11 = fmaxf(r1, c1);
            m[k] = v00 * (1.0f - fx) * (1.0f - fy)
                 + v01 * fx          * (1.0f - fy)
                 + v10 * (1.0f - fx) * fy
                 + v11 * fx          * fy;
        }

        const size_t base = ((size_t)h * WW + w) * 3;
        float4* dst = reinterpret_cast<float4*>(outb + base);

        if (m[0] == 0.0f && m[1] == 0.0f && m[2] == 0.0f && m[3] == 0.0f) {
            // exact zero region: skip the image read entirely
            float4 z = make_float4(0.f, 0.f, 0.f, 0.f);
            dst[0] = z; dst[1] = z; dst[2] = z;
        } else {
            const float4* src = reinterpret_cast<const float4*>(imgb + base);
            float4 a0 = src[0], a1 = src[1], a2 = src[2];
            dst[0] = make_float4(a0.x * m[0], a0.y * m[0], a0.z * m[0], a0.w * m[1]);
            dst[1] = make_float4(a1.x * m[1], a1.y * m[1], a1.z * m[2], a1.w * m[2]);
            dst[2] = make_float4(a2.x * m[2], a2.y * m[3], a2.z * m[3], a2.w * m[3]);
        }
    }
}

extern "C" void kernel_launch(void* const* d_in, const int* in_sizes, int n_in,
                              void* d_out, int out_size) {
    const float* images    = (const float*)d_in[0];
    const float* angles    = (const float*)d_in[1];
    const int*   gridblock = (const int*)  d_in[2];
    const int*   start1    = (const int*)  d_in[3];
    const int*   start2    = (const int*)  d_in[4];
    float* out = (float*)d_out;

    dim3 grid(HH / 8, BB);   // (64, 32)
    gridmask_kernel<<<grid, 256>>>(images, angles, gridblock, start1, start2, out);
}